// round 3
// baseline (speedup 1.0000x reference)
#include <cuda_runtime.h>
#include <cstdint>

// NeuralODE fused RK4 integrator, tf32 mma.sync engine.
// One kernel, whole 64-step integration. Per block: 128 batch rows, 8 warps x 16 rows.
// Weights pre-arranged in SMEM in m16n8k8 B-fragment order (1 LDS.64 per fragment).

#define D_IN      64
#define HID       256
#define MROWS     16      // rows per warp
#define NWARPS    8
#define BLK_ROWS  128     // MROWS * NWARPS
#define NTHREADS  256
#define NSTEPS    64
#define CHUNK_NT  4       // 4 n-tiles of 8 = 32 hidden cols per chunk
#define NCHUNKS   8       // HID / 32

#define YT_STRIDE 68      // pad: conflict-free A-fragment loads
#define HB_STRIDE 36

// SMEM layout (floats)
#define W1F_OFF   0                    // 16384
#define W2F_OFF   16384                // 16384
#define B1_OFF    32768                // 256
#define B2_OFF    33024                // 64
#define WST_OFF   33088                // per-warp state: 2752 floats each
#define WST_FLOATS 2752                // y0:16*68 + yt:16*68 + hb:16*36
#define SMEM_FLOATS (33088 + 8*2752)   // 55104
#define SMEM_BYTES  (SMEM_FLOATS * 4)  // 220416

__device__ __forceinline__ float to_tf32(float x) {
    uint32_t u;
    asm("cvt.rna.tf32.f32 %0, %1;" : "=r"(u) : "f"(x));
    return __uint_as_float(u);
}

__device__ __forceinline__ void mma_tf32(float c[4],
                                         uint32_t a0, uint32_t a1, uint32_t a2, uint32_t a3,
                                         uint32_t b0, uint32_t b1) {
    asm volatile(
        "mma.sync.aligned.m16n8k8.row.col.f32.tf32.tf32.f32 "
        "{%0,%1,%2,%3}, {%4,%5,%6,%7}, {%8,%9}, {%0,%1,%2,%3};\n"
        : "+f"(c[0]), "+f"(c[1]), "+f"(c[2]), "+f"(c[3])
        : "r"(a0), "r"(a1), "r"(a2), "r"(a3), "r"(b0), "r"(b1));
}

__device__ __forceinline__ float elu_f(float v) {
    float e = __expf(v) - 1.0f;
    return v > 0.0f ? v : e;
}

__global__ void __launch_bounds__(NTHREADS, 1)
node_rk4_kernel(const float* __restrict__ x,
                const float* __restrict__ tptr,
                const float* __restrict__ W1,   // [256,64] row-major
                const float* __restrict__ b1,   // [256]
                const float* __restrict__ W2,   // [64,256] row-major
                const float* __restrict__ b2,   // [64]
                float* __restrict__ out,
                int n_rows) {
    extern __shared__ float smem[];
    float* W1f = smem + W1F_OFF;
    float* W2f = smem + W2F_OFF;
    float* b1s = smem + B1_OFF;
    float* b2s = smem + B2_OFF;

    const int tid  = threadIdx.x;
    const int lane = tid & 31;
    const int warp = tid >> 5;
    const int g    = lane >> 2;   // groupID 0..7
    const int tq   = lane & 3;    // threadID-in-group 0..3

    float* wst = smem + WST_OFF + warp * WST_FLOATS;
    float* y0s = wst;                       // [16][68] fp32
    float* yts = wst + MROWS * YT_STRIDE;   // [16][68] tf32-rounded
    float* hb  = yts + MROWS * YT_STRIDE;   // [16][36] tf32-rounded

    // ---- init: weights into fragment-ordered SMEM (tf32-rounded) ----
    // W1 B-fragment: tile = kt*32 + ntg (kt 0..7, ntg 0..31); elem idx = tile*64 + lane_*2 + j
    // value = W1T[k][n] = W1[n][k], k = kt*8 + (lane_&3) + 4*j, n = ntg*8 + (lane_>>2)
    for (int i = tid; i < 16384; i += NTHREADS) {
        int j = i & 1, ln = (i >> 1) & 31, tile = i >> 6;
        int kt = tile >> 5, ntg = tile & 31;
        int k = kt * 8 + (ln & 3) + (j ? 4 : 0);
        int n = ntg * 8 + (ln >> 2);
        W1f[i] = to_tf32(W1[n * D_IN + k]);
    }
    // W2 B-fragment: tile = ktg*8 + nt (ktg 0..31, nt 0..7)
    // value = W2T[k][n] = W2[n][k], k = ktg*8 + (lane_&3) + 4*j, n = nt*8 + (lane_>>2)
    for (int i = tid; i < 16384; i += NTHREADS) {
        int j = i & 1, ln = (i >> 1) & 31, tile = i >> 6;
        int ktg = tile >> 3, nt = tile & 7;
        int k = ktg * 8 + (ln & 3) + (j ? 4 : 0);
        int n = nt * 8 + (ln >> 2);
        W2f[i] = to_tf32(W2[n * HID + k]);
    }
    for (int i = tid; i < HID; i += NTHREADS) b1s[i] = b1[i];
    for (int i = tid; i < D_IN; i += NTHREADS) b2s[i] = b2[i];

    // ---- init: load y0 (fp32) and yt (tf32) ----
    const int row0 = blockIdx.x * BLK_ROWS;
    for (int i = tid; i < BLK_ROWS * D_IN; i += NTHREADS) {
        int r = i >> 6, c = i & 63;
        float v = x[(size_t)(row0 + r) * D_IN + c];
        float* ws = smem + WST_OFF + (r >> 4) * WST_FLOATS;
        int lr = r & 15;
        ws[lr * YT_STRIDE + c] = v;
        ws[MROWS * YT_STRIDE + lr * YT_STRIDE + c] = to_tf32(v);
    }
    __syncthreads();

    const float t0 = tptr[0];
    const float dt = t0 * 0.015625f;   // t0/64
    const float half_dt = 0.5f * dt;
    const float dt6 = dt * (1.0f / 6.0f);

    float rk4[8][4];

    for (int step = 0; step < NSTEPS; ++step) {
#pragma unroll 1
        for (int s = 0; s < 4; ++s) {
            float kacc[8][4];
#pragma unroll
            for (int nt = 0; nt < 8; ++nt)
#pragma unroll
                for (int j = 0; j < 4; ++j) kacc[nt][j] = 0.0f;

#pragma unroll 1
            for (int nc = 0; nc < NCHUNKS; ++nc) {
                // ---- GEMM1 chunk: h[16, 32] = yt[16,64] @ W1T[64, 32cols] ----
                float c1[CHUNK_NT][4];
#pragma unroll
                for (int nt = 0; nt < CHUNK_NT; ++nt)
#pragma unroll
                    for (int j = 0; j < 4; ++j) c1[nt][j] = 0.0f;

#pragma unroll
                for (int kt = 0; kt < 8; ++kt) {
                    int ka = kt * 8 + tq;
                    uint32_t a0 = __float_as_uint(yts[g * YT_STRIDE + ka]);
                    uint32_t a1 = __float_as_uint(yts[(g + 8) * YT_STRIDE + ka]);
                    uint32_t a2 = __float_as_uint(yts[g * YT_STRIDE + ka + 4]);
                    uint32_t a3 = __float_as_uint(yts[(g + 8) * YT_STRIDE + ka + 4]);
#pragma unroll
                    for (int nt = 0; nt < CHUNK_NT; ++nt) {
                        const float2 b = *(const float2*)(W1f + ((kt * 32 + nc * 4 + nt) * 64 + lane * 2));
                        mma_tf32(c1[nt], a0, a1, a2, a3,
                                 __float_as_uint(b.x), __float_as_uint(b.y));
                    }
                }

                __syncwarp();   // prior chunk's hb reads done before overwrite
                // ---- bias + ELU + tf32 round -> hb staging ----
#pragma unroll
                for (int nt = 0; nt < CHUNK_NT; ++nt) {
                    int n0 = nc * 32 + nt * 8;
                    int cc0 = n0 + 2 * tq;
                    float bb0 = b1s[cc0], bb1 = b1s[cc0 + 1];
                    float v00 = elu_f(c1[nt][0] + bb0);
                    float v01 = elu_f(c1[nt][1] + bb1);
                    float v10 = elu_f(c1[nt][2] + bb0);
                    float v11 = elu_f(c1[nt][3] + bb1);
                    int hc0 = nt * 8 + 2 * tq;
                    hb[g * HB_STRIDE + hc0]           = to_tf32(v00);
                    hb[g * HB_STRIDE + hc0 + 1]       = to_tf32(v01);
                    hb[(g + 8) * HB_STRIDE + hc0]     = to_tf32(v10);
                    hb[(g + 8) * HB_STRIDE + hc0 + 1] = to_tf32(v11);
                }
                __syncwarp();

                // ---- GEMM2 partial: kacc += h_chunk[16,32] @ W2T[32cols, 64] ----
#pragma unroll
                for (int kt2 = 0; kt2 < 4; ++kt2) {
                    int ka = kt2 * 8 + tq;
                    uint32_t a0 = __float_as_uint(hb[g * HB_STRIDE + ka]);
                    uint32_t a1 = __float_as_uint(hb[(g + 8) * HB_STRIDE + ka]);
                    uint32_t a2 = __float_as_uint(hb[g * HB_STRIDE + ka + 4]);
                    uint32_t a3 = __float_as_uint(hb[(g + 8) * HB_STRIDE + ka + 4]);
#pragma unroll
                    for (int nt2 = 0; nt2 < 8; ++nt2) {
                        const float2 b = *(const float2*)(W2f + (((nc * 4 + kt2) * 8 + nt2) * 64 + lane * 2));
                        mma_tf32(kacc[nt2], a0, a1, a2, a3,
                                 __float_as_uint(b.x), __float_as_uint(b.y));
                    }
                }
            } // nc

            // ---- add b2; k = kacc is f(yt) in C-fragment layout ----
#pragma unroll
            for (int nt2 = 0; nt2 < 8; ++nt2) {
                int c0 = nt2 * 8 + 2 * tq;
                float bb0 = b2s[c0], bb1 = b2s[c0 + 1];
                kacc[nt2][0] += bb0; kacc[nt2][1] += bb1;
                kacc[nt2][2] += bb0; kacc[nt2][3] += bb1;
            }

            const float wk = (s == 1 || s == 2) ? 2.0f : 1.0f;
            if (s == 0) {
#pragma unroll
                for (int nt2 = 0; nt2 < 8; ++nt2)
#pragma unroll
                    for (int j = 0; j < 4; ++j) rk4[nt2][j] = kacc[nt2][j];
            } else {
#pragma unroll
                for (int nt2 = 0; nt2 < 8; ++nt2)
#pragma unroll
                    for (int j = 0; j < 4; ++j) rk4[nt2][j] += wk * kacc[nt2][j];
            }

            if (s < 3) {
                const float cn = (s == 2) ? dt : half_dt;
#pragma unroll
                for (int nt2 = 0; nt2 < 8; ++nt2) {
                    int c0 = nt2 * 8 + 2 * tq;
                    int p00 = g * YT_STRIDE + c0;
                    int p10 = (g + 8) * YT_STRIDE + c0;
                    yts[p00]     = to_tf32(y0s[p00]     + cn * kacc[nt2][0]);
                    yts[p00 + 1] = to_tf32(y0s[p00 + 1] + cn * kacc[nt2][1]);
                    yts[p10]     = to_tf32(y0s[p10]     + cn * kacc[nt2][2]);
                    yts[p10 + 1] = to_tf32(y0s[p10 + 1] + cn * kacc[nt2][3]);
                }
            } else {
                // y0 += dt/6 * (k1 + 2k2 + 2k3 + k4); yt = tf32(y0)
#pragma unroll
                for (int nt2 = 0; nt2 < 8; ++nt2) {
                    int c0 = nt2 * 8 + 2 * tq;
                    int p00 = g * YT_STRIDE + c0;
                    int p10 = (g + 8) * YT_STRIDE + c0;
                    float y00 = y0s[p00]     + dt6 * rk4[nt2][0];
                    float y01 = y0s[p00 + 1] + dt6 * rk4[nt2][1];
                    float y10 = y0s[p10]     + dt6 * rk4[nt2][2];
                    float y11 = y0s[p10 + 1] + dt6 * rk4[nt2][3];
                    y0s[p00] = y00;     yts[p00] = to_tf32(y00);
                    y0s[p00 + 1] = y01; yts[p00 + 1] = to_tf32(y01);
                    y0s[p10] = y10;     yts[p10] = to_tf32(y10);
                    y0s[p10 + 1] = y11; yts[p10 + 1] = to_tf32(y11);
                }
            }
            __syncwarp();
        } // stage
    } // step

    // ---- write result (coalesced) ----
    __syncthreads();
    for (int i = tid; i < BLK_ROWS * D_IN; i += NTHREADS) {
        int r = i >> 6, c = i & 63;
        const float* ws = smem + WST_OFF + (r >> 4) * WST_FLOATS;
        out[(size_t)(row0 + r) * D_IN + c] = ws[(r & 15) * YT_STRIDE + c];
    }
}

extern "C" void kernel_launch(void* const* d_in, const int* in_sizes, int n_in,
                              void* d_out, int out_size) {
    const float* x  = (const float*)d_in[0];
    const float* t  = (const float*)d_in[1];
    const float* W1 = (const float*)d_in[2];
    const float* b1 = (const float*)d_in[3];
    const float* W2 = (const float*)d_in[4];
    const float* b2 = (const float*)d_in[5];
    float* out = (float*)d_out;

    int n_rows = in_sizes[0] / D_IN;           // 262144
    int grid = n_rows / BLK_ROWS;              // 2048

    cudaFuncSetAttribute(node_rk4_kernel,
                         cudaFuncAttributeMaxDynamicSharedMemorySize, SMEM_BYTES);
    node_rk4_kernel<<<grid, NTHREADS, SMEM_BYTES>>>(x, t, W1, b1, W2, b2, out, n_rows);
}

// round 7
// speedup vs baseline: 2.6350x; 2.6350x over previous
#include <cuda_runtime.h>
#include <cuda_bf16.h>
#include <cstdint>

// NeuralODE fused RK4, bf16 mma.sync m16n8k16 engine, fully register-resident state.
// Per CTA: 128 rows, 8 warps x 16 rows, whole 64-step RK4 (256 f-evals).
// SMEM: only pre-packed B-fragment weights (bf16) + biases. No state staging, no
// sync in the main loop. GEMM1 C-fragments are reused in-register as GEMM2
// A-fragments (layout identity), and the y-update C-fragments become next A1 frags.

#define D_IN      64
#define HID       256
#define NWARPS    8
#define BLK_ROWS  128
#define NTHREADS  256
#define NSTEPS    64

// SMEM (bytes): W1 frags 32KB, W2 frags 32KB, b1 1KB, b2 256B
#define W1F_OFF   0        // u32[8192]
#define W2F_OFF   32768    // u32[8192]
#define B1_OFF    65536    // float[256]
#define B2_OFF    66560    // float[64]
#define SMEM_BYTES 66816

__device__ __forceinline__ uint32_t pack_bf16(float lo, float hi) {
    uint32_t r;
    asm("cvt.rn.bf16x2.f32 %0, %1, %2;" : "=r"(r) : "f"(hi), "f"(lo));
    return r;
}

__device__ __forceinline__ void mma_bf16(float c[4],
                                         uint32_t a0, uint32_t a1, uint32_t a2, uint32_t a3,
                                         uint32_t b0, uint32_t b1) {
    asm volatile(
        "mma.sync.aligned.m16n8k16.row.col.f32.bf16.bf16.f32 "
        "{%0,%1,%2,%3}, {%4,%5,%6,%7}, {%8,%9}, {%0,%1,%2,%3};\n"
        : "+f"(c[0]), "+f"(c[1]), "+f"(c[2]), "+f"(c[3])
        : "r"(a0), "r"(a1), "r"(a2), "r"(a3), "r"(b0), "r"(b1));
}

__device__ __forceinline__ float elu_f(float v) {
    float e = __expf(v) - 1.0f;
    return v > 0.0f ? v : e;
}

__global__ void __launch_bounds__(NTHREADS, 1)
node_rk4_bf16_kernel(const float* __restrict__ x,
                     const float* __restrict__ tptr,
                     const float* __restrict__ W1,   // [256,64] row-major
                     const float* __restrict__ b1,   // [256]
                     const float* __restrict__ W2,   // [64,256] row-major
                     const float* __restrict__ b2,   // [64]
                     float* __restrict__ out) {
    extern __shared__ char smem_c[];
    uint32_t* W1f = (uint32_t*)(smem_c + W1F_OFF);
    uint32_t* W2f = (uint32_t*)(smem_c + W2F_OFF);
    float*    b1s = (float*)(smem_c + B1_OFF);
    float*    b2s = (float*)(smem_c + B2_OFF);

    const int tid  = threadIdx.x;
    const int lane = tid & 31;
    const int warp = tid >> 5;
    const int g    = lane >> 2;   // 0..7
    const int tq   = lane & 3;    // 0..3

    // ---- init: W1 B-fragments (K=64 -> 4 ktiles; N=256 -> 32 ntiles) ----
    // tile idx = nt*4 + kt; u32 slot = tile*64 + ln*2 + j
    // j=0: {B[2tq][g], B[2tq+1][g]}   j=1: {B[2tq+8][g], B[2tq+9][g]}
    // B1[k][n] = W1[n][k]
    for (int i = tid; i < 8192; i += NTHREADS) {
        int j = i & 1, ln = (i >> 1) & 31, tile = i >> 6;
        int nt = tile >> 2, kt = tile & 3;
        int n = nt * 8 + (ln >> 2);
        int k = kt * 16 + 2 * (ln & 3) + (j ? 8 : 0);
        const float2 w = *(const float2*)(W1 + n * D_IN + k);
        W1f[i] = pack_bf16(w.x, w.y);
    }
    // ---- W2 B-fragments (K=256 -> 16 ktiles; N=64 -> 8 ntiles) ----
    // tile idx = kt2*8 + nt2;  B2[k][n] = W2[n][k]
    for (int i = tid; i < 8192; i += NTHREADS) {
        int j = i & 1, ln = (i >> 1) & 31, tile = i >> 6;
        int kt2 = tile >> 3, nt2 = tile & 7;
        int n = nt2 * 8 + (ln >> 2);
        int k = kt2 * 16 + 2 * (ln & 3) + (j ? 8 : 0);
        const float2 w = *(const float2*)(W2 + n * HID + k);
        W2f[i] = pack_bf16(w.x, w.y);
    }
    for (int i = tid; i < HID; i += NTHREADS) b1s[i] = b1[i];
    for (int i = tid; i < D_IN; i += NTHREADS) b2s[i] = b2[i];
    __syncthreads();

    const float t0 = tptr[0];
    const float dt = t0 * 0.015625f;
    const float half_dt = 0.5f * dt;
    const float dt6 = dt * (1.0f / 6.0f);

    // ---- load x in C-fragment layout: y0[nt][0..3] ----
    const int rbase = blockIdx.x * BLK_ROWS + warp * 16;
    float y0[8][4];
    {
        const float* xr0 = x + (size_t)(rbase + g) * D_IN + 2 * tq;
        const float* xr1 = x + (size_t)(rbase + g + 8) * D_IN + 2 * tq;
#pragma unroll
        for (int nt = 0; nt < 8; ++nt) {
            float2 u = *(const float2*)(xr0 + nt * 8);
            float2 v = *(const float2*)(xr1 + nt * 8);
            y0[nt][0] = u.x; y0[nt][1] = u.y;
            y0[nt][2] = v.x; y0[nt][3] = v.y;
        }
    }

    // A1 fragments of y (bf16): a1f[kt*4 + r], kt = 0..3
    uint32_t a1f[16];
#pragma unroll
    for (int kt = 0; kt < 4; ++kt) {
        a1f[kt * 4 + 0] = pack_bf16(y0[2 * kt][0],     y0[2 * kt][1]);
        a1f[kt * 4 + 1] = pack_bf16(y0[2 * kt][2],     y0[2 * kt][3]);
        a1f[kt * 4 + 2] = pack_bf16(y0[2 * kt + 1][0], y0[2 * kt + 1][1]);
        a1f[kt * 4 + 3] = pack_bf16(y0[2 * kt + 1][2], y0[2 * kt + 1][3]);
    }

    float rk4[8][4];

#pragma unroll 1
    for (int e = 0; e < NSTEPS * 4; ++e) {
        const int s = e & 3;

        float kacc[8][4];
#pragma unroll
        for (int nt = 0; nt < 8; ++nt)
#pragma unroll
            for (int j = 0; j < 4; ++j) kacc[nt][j] = 0.0f;

#pragma unroll
        for (int nc = 0; nc < 8; ++nc) {
            // ---- GEMM1 chunk: 4 ntiles (32 hidden cols), K=64 ----
            float c1[4][4];
#pragma unroll
            for (int nt = 0; nt < 4; ++nt)
#pragma unroll
                for (int j = 0; j < 4; ++j) c1[nt][j] = 0.0f;

#pragma unroll
            for (int kt = 0; kt < 4; ++kt) {
#pragma unroll
                for (int nt = 0; nt < 4; ++nt) {
                    const uint2 b = *(const uint2*)(W1f + (((nc * 4 + nt) * 4 + kt) * 64 + lane * 2));
                    mma_bf16(c1[nt], a1f[kt * 4], a1f[kt * 4 + 1], a1f[kt * 4 + 2], a1f[kt * 4 + 3],
                             b.x, b.y);
                }
            }

            // ---- bias + ELU + pack: C-frags become GEMM2 A-frags in registers ----
            uint32_t hf[2][4];
#pragma unroll
            for (int nt = 0; nt < 4; ++nt) {
                const float2 bb = *(const float2*)(b1s + (nc * 32 + nt * 8 + 2 * tq));
                float v00 = elu_f(c1[nt][0] + bb.x);
                float v01 = elu_f(c1[nt][1] + bb.y);
                float v10 = elu_f(c1[nt][2] + bb.x);
                float v11 = elu_f(c1[nt][3] + bb.y);
                hf[nt >> 1][(nt & 1) * 2 + 0] = pack_bf16(v00, v01);
                hf[nt >> 1][(nt & 1) * 2 + 1] = pack_bf16(v10, v11);
            }

            // ---- GEMM2 partial: 2 ktiles of 16 (this chunk's 32 hidden cols) ----
#pragma unroll
            for (int ktl = 0; ktl < 2; ++ktl) {
#pragma unroll
                for (int nt2 = 0; nt2 < 8; ++nt2) {
                    const uint2 b = *(const uint2*)(W2f + (((nc * 2 + ktl) * 8 + nt2) * 64 + lane * 2));
                    mma_bf16(kacc[nt2], hf[ktl][0], hf[ktl][1], hf[ktl][2], hf[ktl][3],
                             b.x, b.y);
                }
            }
        } // nc

        // ---- epilogue: k = kacc + b2; RK4 update; repack A1 frags ----
        const float wk = (s == 1 || s == 2) ? 2.0f : 1.0f;
        const float cn = (s == 2) ? dt : half_dt;
        float yn[8][4];
#pragma unroll
        for (int nt = 0; nt < 8; ++nt) {
            const float2 bb = *(const float2*)(b2s + (nt * 8 + 2 * tq));
            float k0 = kacc[nt][0] + bb.x;
            float k1 = kacc[nt][1] + bb.y;
            float k2 = kacc[nt][2] + bb.x;
            float k3 = kacc[nt][3] + bb.y;
            if (s == 0) {
                rk4[nt][0] = k0; rk4[nt][1] = k1; rk4[nt][2] = k2; rk4[nt][3] = k3;
            } else {
                rk4[nt][0] += wk * k0; rk4[nt][1] += wk * k1;
                rk4[nt][2] += wk * k2; rk4[nt][3] += wk * k3;
            }
            if (s < 3) {
                yn[nt][0] = y0[nt][0] + cn * k0;
                yn[nt][1] = y0[nt][1] + cn * k1;
                yn[nt][2] = y0[nt][2] + cn * k2;
                yn[nt][3] = y0[nt][3] + cn * k3;
            } else {
                y0[nt][0] += dt6 * rk4[nt][0];
                y0[nt][1] += dt6 * rk4[nt][1];
                y0[nt][2] += dt6 * rk4[nt][2];
                y0[nt][3] += dt6 * rk4[nt][3];
                yn[nt][0] = y0[nt][0]; yn[nt][1] = y0[nt][1];
                yn[nt][2] = y0[nt][2]; yn[nt][3] = y0[nt][3];
            }
        }
#pragma unroll
        for (int kt = 0; kt < 4; ++kt) {
            a1f[kt * 4 + 0] = pack_bf16(yn[2 * kt][0],     yn[2 * kt][1]);
            a1f[kt * 4 + 1] = pack_bf16(yn[2 * kt][2],     yn[2 * kt][3]);
            a1f[kt * 4 + 2] = pack_bf16(yn[2 * kt + 1][0], yn[2 * kt + 1][1]);
            a1f[kt * 4 + 3] = pack_bf16(yn[2 * kt + 1][2], yn[2 * kt + 1][3]);
        }
    } // eval loop

    // ---- write final y0 ----
    {
        float* or0 = out + (size_t)(rbase + g) * D_IN + 2 * tq;
        float* or1 = out + (size_t)(rbase + g + 8) * D_IN + 2 * tq;
#pragma unroll
        for (int nt = 0; nt < 8; ++nt) {
            *(float2*)(or0 + nt * 8) = make_float2(y0[nt][0], y0[nt][1]);
            *(float2*)(or1 + nt * 8) = make_float2(y0[nt][2], y0[nt][3]);
        }
    }
}

extern "C" void kernel_launch(void* const* d_in, const int* in_sizes, int n_in,
                              void* d_out, int out_size) {
    const float* x  = (const float*)d_in[0];
    const float* t  = (const float*)d_in[1];
    const float* W1 = (const float*)d_in[2];
    const float* b1 = (const float*)d_in[3];
    const float* W2 = (const float*)d_in[4];
    const float* b2 = (const float*)d_in[5];
    float* out = (float*)d_out;

    int n_rows = in_sizes[0] / D_IN;      // 262144
    int grid = n_rows / BLK_ROWS;         // 2048

    cudaFuncSetAttribute(node_rk4_bf16_kernel,
                         cudaFuncAttributeMaxDynamicSharedMemorySize, SMEM_BYTES);
    node_rk4_bf16_kernel<<<grid, NTHREADS, SMEM_BYTES>>>(x, t, W1, b1, W2, b2, out);
}